// round 14
// baseline (speedup 1.0000x reference)
#include <cuda_runtime.h>
#include <math.h>

#define RS2 0.70710678f // 1/sqrt(2)

typedef unsigned long long u64;

// packed f32x2 FMA (lanewise fp32 fma): d = a*b + d
#define FMA2(d, a, b) asm("fma.rn.f32x2 %0, %1, %2, %0;" : "+l"(d) : "l"(a), "l"(b))

__device__ __forceinline__ u64 dup2(float w) {
    u64 r;
    asm("mov.b64 %0, {%1, %1};" : "=l"(r) : "r"(__float_as_uint(w)));
    return r;
}

// ---- scratch (device globals; no allocation allowed) ----
__device__ float g_s  [4*4*256*32*32];      // spikes (0/1)
__device__ float g_l1 [16*512*32*16];       // pre-BN level-1 coeffs
__device__ float g_l2 [16*1024*16*16];      // pre-BN level-2 coeffs
__device__ float g_rec[16*256*32*32];       // pre-BN reconstruction
__device__ float g_c1 [16*256*32*32];       // pre-BN conv1 out
__device__ float g_c2 [16*256*32*32];       // pre-BN conv2 out
// per-(channel, slot) partial (sum, sumsq) — fixed slots => deterministic
__device__ float2 g_part_fwd[512*8];
__device__ float2 g_part_mul[1024*16];
__device__ float2 g_part_inv[256*16];
__device__ float2 g_part_c1 [256*32];
__device__ float2 g_part_c2 [256*32];

// ============================================================
// K1: LIF over T + Haar along W + L1 gate + bn_fwd partials
// ============================================================
__global__ void k_lif_haarw(const float* __restrict__ x) {
    int blk = blockIdx.x, t = threadIdx.x;
    int idx = blk * 256 + t;
    int wp = idx & 15;
    int h  = (idx >> 4) & 31;
    int c  = (idx >> 9) & 255;
    int b  = idx >> 17;

    float v0 = 0.f, v1 = 0.f;
    float4 ps = make_float4(0.f, 0.f, 0.f, 0.f);
    #pragma unroll
    for (int tt = 0; tt < 4; tt++) {
        size_t base = ((((size_t)tt*4 + b)*256 + c)*32 + h)*32 + 2*wp;
        float2 xx = *reinterpret_cast<const float2*>(&x[base]);
        v0 += (xx.x - v0) * 0.5f;
        float s0 = (v0 >= 1.0f) ? 1.0f : 0.0f;
        v0 *= (1.0f - s0);
        v1 += (xx.y - v1) * 0.5f;
        float s1 = (v1 >= 1.0f) ? 1.0f : 0.0f;
        v1 *= (1.0f - s1);
        *reinterpret_cast<float2*>(&g_s[base]) = make_float2(s0, s1);

        float low  = RS2 * (s0 + s1);
        float high = RS2 * (s0 - s1);
        if (fabsf(low)  < 0.5f) low  = 0.f;
        if (fabsf(high) < 0.5f) high = 0.f;
        int tb = tt*4 + b;
        size_t l1b = (((size_t)tb*512 + c)*32 + h)*16 + wp;
        g_l1[l1b]          = low;
        g_l1[l1b + 131072] = high;
        ps.x += low;  ps.y += low*low;
        ps.z += high; ps.w += high*high;
    }
    #pragma unroll
    for (int off = 16; off; off >>= 1) {
        ps.x += __shfl_down_sync(0xffffffffu, ps.x, off);
        ps.y += __shfl_down_sync(0xffffffffu, ps.y, off);
        ps.z += __shfl_down_sync(0xffffffffu, ps.z, off);
        ps.w += __shfl_down_sync(0xffffffffu, ps.w, off);
    }
    __shared__ float4 wsum[8];
    if ((t & 31) == 0) wsum[t >> 5] = ps;
    __syncthreads();
    if (t == 0) {
        float4 a = wsum[0];
        #pragma unroll
        for (int i = 1; i < 8; i++) {
            float4 w4 = wsum[i];
            a.x += w4.x; a.y += w4.y; a.z += w4.z; a.w += w4.w;
        }
        int slot = ((blk >> 9) << 1) | (blk & 1);   // b*2 + hhalf
        int cc   = (blk >> 1) & 255;
        g_part_fwd[cc*8 + slot]         = make_float2(a.x, a.y);
        g_part_fwd[(256 + cc)*8 + slot] = make_float2(a.z, a.w);
    }
}

// ============================================================
// K2: inline bn_fwd stats + Haar along H + threshold + band gate
//     + bn_mul partials. block <-> (tb, c)
// ============================================================
__global__ void k_haarh_gate(const float* __restrict__ gf,
                             const float* __restrict__ bf) {
    int tb = blockIdx.x >> 8;
    int c  = blockIdx.x & 255;
    int t  = threadIdx.x;

    __shared__ float2 coef[2];
    if (t < 16) {
        int chn = (t < 8) ? c : 256 + c;
        float2 p = g_part_fwd[chn*8 + (t & 7)];
        float s = p.x, q = p.y;
        #pragma unroll
        for (int off = 4; off; off >>= 1) {
            s += __shfl_down_sync(0xffffu, s, off, 8);
            q += __shfl_down_sync(0xffffu, q, off, 8);
        }
        if ((t & 7) == 0) {
            float mean = s * (1.0f/8192.0f);
            float var  = q * (1.0f/8192.0f) - mean*mean;
            float a = gf[chn] * rsqrtf(var + 1e-5f);
            coef[t >> 3] = make_float2(a, bf[chn] - mean*a);
        }
    }
    __syncthreads();

    int v = t >> 4, w = t & 15;
    float alo = coef[0].x, clo = coef[0].y;
    float ahi = coef[1].x, chi = coef[1].y;

    size_t lo_base = ((size_t)tb*512 + c) * 512;
    size_t hi_base = lo_base + 131072;
    float a0 = g_l1[lo_base + (2*v  )*16 + w] * alo + clo;
    float a1 = g_l1[lo_base + (2*v+1)*16 + w] * alo + clo;
    float b0 = g_l1[hi_base + (2*v  )*16 + w] * ahi + chi;
    float b1 = g_l1[hi_base + (2*v+1)*16 + w] * ahi + chi;

    float LL = RS2 * (a0 + a1);
    float HL = RS2 * (a0 - a1);
    float LH = RS2 * (b0 + b1);
    float HH = RS2 * (b0 - b1);
    if (fabsf(LL) < 0.5f) LL = 0.f;
    if (fabsf(HL) < 0.5f) HL = 0.f;
    if (fabsf(LH) < 0.5f) LH = 0.f;
    if (fabsf(HH) < 0.5f) HH = 0.f;

    float4 vs = make_float4(LL, HL, LH, HH);
    float4 vq = make_float4(LL*LL, HL*HL, LH*LH, HH*HH);
    #pragma unroll
    for (int off = 16; off; off >>= 1) {
        vs.x += __shfl_down_sync(0xffffffffu, vs.x, off);
        vs.y += __shfl_down_sync(0xffffffffu, vs.y, off);
        vs.z += __shfl_down_sync(0xffffffffu, vs.z, off);
        vs.w += __shfl_down_sync(0xffffffffu, vs.w, off);
        vq.x += __shfl_down_sync(0xffffffffu, vq.x, off);
        vq.y += __shfl_down_sync(0xffffffffu, vq.y, off);
        vq.z += __shfl_down_sync(0xffffffffu, vq.z, off);
        vq.w += __shfl_down_sync(0xffffffffu, vq.w, off);
    }
    __shared__ float4 wS[8], wQ[8];
    __shared__ float4 flags;
    if ((t & 31) == 0) { wS[t >> 5] = vs; wQ[t >> 5] = vq; }
    __syncthreads();
    if (t == 0) {
        float4 S = wS[0], Q = wQ[0];
        #pragma unroll
        for (int i = 1; i < 8; i++) {
            float4 a = wS[i], b4 = wQ[i];
            S.x += a.x;  S.y += a.y;  S.z += a.z;  S.w += a.w;
            Q.x += b4.x; Q.y += b4.y; Q.z += b4.z; Q.w += b4.w;
        }
        const float inv = 1.0f / 256.0f;
        float4 f = make_float4(Q.x*inv > 0.01f ? 1.f : 0.f,
                               Q.y*inv > 0.02f ? 1.f : 0.f,
                               Q.z*inv > 0.02f ? 1.f : 0.f,
                               Q.w*inv > 0.05f ? 1.f : 0.f);
        flags = f;
        g_part_mul[(c      )*16 + tb] = make_float2(f.x*S.x, f.x*Q.x);
        g_part_mul[(c + 256)*16 + tb] = make_float2(f.y*S.y, f.y*Q.y);
        g_part_mul[(c + 512)*16 + tb] = make_float2(f.z*S.z, f.z*Q.z);
        g_part_mul[(c + 768)*16 + tb] = make_float2(f.w*S.w, f.w*Q.w);
    }
    __syncthreads();

    size_t ob = (((size_t)tb*1024 + c)*16 + v)*16 + w;
    g_l2[ob]          = LL * flags.x;
    g_l2[ob + 65536]  = HL * flags.y;
    g_l2[ob + 131072] = LH * flags.z;
    g_l2[ob + 196608] = HH * flags.w;
}

// ============================================================
// K3 (fused): bn_mul stats + 16x16 channel mix for all 4 subbands of a
// base group + inverse Haar butterfly + bn_inv partials.
// ============================================================
__global__ void k_mix_inv(const float* __restrict__ hw,
                          const float* __restrict__ gm,
                          const float* __restrict__ bm) {
    int tb = blockIdx.x >> 4;
    int gb = blockIdx.x & 15;
    int t  = threadIdx.x;

    __shared__ float Wsm[4][256];
    __shared__ float sc[64], of[64];
    __shared__ float2 wred[8][16];

    #pragma unroll
    for (int sb = 0; sb < 4; sb++)
        Wsm[sb][t] = hw[(4*sb + (gb >> 2)) * 256 + t];

    {
        int chl = t >> 2, j = t & 3;
        int sb = chl >> 4, d = chl & 15;
        int ch = sb*256 + gb*16 + d;
        float s = 0.f, q = 0.f;
        #pragma unroll
        for (int k = 0; k < 4; k++) {
            float2 p = g_part_mul[ch*16 + j + 4*k];
            s += p.x; q += p.y;
        }
        s += __shfl_down_sync(0xffffffffu, s, 2, 4);
        q += __shfl_down_sync(0xffffffffu, q, 2, 4);
        s += __shfl_down_sync(0xffffffffu, s, 1, 4);
        q += __shfl_down_sync(0xffffffffu, q, 1, 4);
        if (j == 0) {
            float mean = s * (1.0f/4096.0f);
            float var  = q * (1.0f/4096.0f) - mean*mean;
            float a = gm[ch] * rsqrtf(var + 1e-5f);
            sc[chl] = a;
            of[chl] = bm[ch] - mean*a;
        }
    }
    __syncthreads();

    float acc[4][16];
    #pragma unroll
    for (int sb = 0; sb < 4; sb++)
        #pragma unroll
        for (int k = 0; k < 16; k++) acc[sb][k] = 0.f;

    #pragma unroll
    for (int sb = 0; sb < 4; sb++) {
        size_t base = ((size_t)tb*1024 + sb*256 + gb*16) * 256 + t;
        #pragma unroll
        for (int d = 0; d < 16; d++) {
            float in = g_l2[base + (size_t)d*256] * sc[sb*16+d] + of[sb*16+d];
            #pragma unroll
            for (int k = 0; k < 16; k++) acc[sb][k] += in * Wsm[sb][d*16 + k];
        }
    }

    int v = t >> 4, w = t & 15;
    int warp = t >> 5;
    #pragma unroll
    for (int k = 0; k < 16; k++) {
        float LL = acc[0][k], HL = acc[1][k], LH = acc[2][k], HH = acc[3][k];
        float lo0 = RS2*(LL + HL), lo1 = RS2*(LL - HL);
        float hi0 = RS2*(LH + HH), hi1 = RS2*(LH - HH);
        float r00 = RS2*(lo0 + hi0), r01 = RS2*(lo0 - hi0);
        float r10 = RS2*(lo1 + hi1), r11 = RS2*(lo1 - hi1);

        size_t rb = (((size_t)tb*256 + gb*16 + k)*32 + 2*v)*32 + 2*w;
        *reinterpret_cast<float2*>(&g_rec[rb])      = make_float2(r00, r01);
        *reinterpret_cast<float2*>(&g_rec[rb + 32]) = make_float2(r10, r11);

        float s = r00 + r01 + r10 + r11;
        float q = r00*r00 + r01*r01 + r10*r10 + r11*r11;
        #pragma unroll
        for (int off = 16; off; off >>= 1) {
            s += __shfl_down_sync(0xffffffffu, s, off);
            q += __shfl_down_sync(0xffffffffu, q, off);
        }
        if ((t & 31) == 0) wred[warp][k] = make_float2(s, q);
    }
    __syncthreads();
    if (t < 16) {
        float S = 0.f, Q = 0.f;
        #pragma unroll
        for (int wd = 0; wd < 8; wd++) { S += wred[wd][t].x; Q += wred[wd][t].y; }
        g_part_inv[(gb*16 + t)*16 + tb] = make_float2(S, Q);
    }
}

// ============================================================
// K4 (fused convs): grouped 3x3 conv (FFMA2) with grouped 1x1 conv on the
// ky==1 leg (tile row h+1 = output row -> E_p is the center-row pair).
// grid 1024 = im x oh(2) x hh(2); 256 thr = 8 oo x 2 wh x 16 h.
// acc[8]+acc1[8] u64 (~85 regs at 256 thr -> no cap, 3 blocks/SM).
// Half-height tiles (18 rows + halo, stride 36, conflict-free).
// + bn_c1/bn_c2 partials (32 slots: tb*2+hh; wh folded in-block).
// ============================================================
#define A_RS 36
#define TCH18 (18 * A_RS)   // 648 floats per channel slab

__global__ __launch_bounds__(256) void k_convs(const float* __restrict__ w2,
                                               const float* __restrict__ w1) {
    int blk = blockIdx.x;                 // 1024
    int im = blk >> 2;
    int oh = (blk >> 1) & 1;
    int hh = blk & 1;
    int tb = im >> 4, nb = im & 15;
    __shared__ __align__(16) float tileA[4 * TCH18];  // 10368 B
    __shared__ __align__(16) float tileB[4 * TCH18];  // 10368 B
    __shared__ float Wsmt[1152];                      //  4608 B  [ic*9+k][oo]
    __shared__ float Wsmt1[128];                      //   512 B  [ic][oo]
    __shared__ float2 red2[8][8], red1[8][8];
    int tid = threadIdx.x;
    int oo = tid & 7;
    int wh = (tid >> 3) & 1;
    int h  = tid >> 4;                    // 0..15

    for (int idx = tid; idx < 1152; idx += 256) {
        int o8 = idx & 7, rest = idx >> 3;          // rest = ic*9+k
        Wsmt[idx] = w2[(oh*8 + o8)*144 + rest];
    }
    if (tid < 128) {
        int o8 = tid & 7, ic = tid >> 3;
        Wsmt1[tid] = w1[(oh*8 + o8)*16 + ic];
    }
    for (int idx = tid; idx < 4*TCH18; idx += 256) { tileA[idx] = 0.f; tileB[idx] = 0.f; }

    size_t sbase = (size_t)im * 16384;
    int base = wh * 8;                    // u64 pair offset within row

    u64 acc[8], acc1[8];
    #pragma unroll
    for (int pl = 0; pl < 8; pl++) { acc[pl] = 0ull; acc1[pl] = 0ull; }

    for (int ph = 0; ph < 4; ph++) {
        __syncthreads();
        // stage 4 channels x 18 rows (rows 16hh-1 .. 16hh+16; halo zeros stay)
        for (int idx = tid; idx < 576; idx += 256) {
            int ii  = idx / 144;
            int rem = idx - ii*144;
            int rr  = rem >> 3;                      // local row 0..17
            int ww4 = (rem & 7) * 4;
            int r = 16*hh + rr - 1;
            if (r >= 0 && r < 32) {
                float4 val = *reinterpret_cast<const float4*>(
                    &g_s[sbase + (size_t)(ph*4 + ii)*1024 + r*32 + ww4]);
                float* dA = &tileA[ii*TCH18 + rr*A_RS + ww4 + 1];
                dA[0] = val.x; dA[1] = val.y; dA[2] = val.z; dA[3] = val.w;
                *reinterpret_cast<float4*>(&tileB[ii*TCH18 + rr*A_RS + ww4]) = val;
            }
        }
        __syncthreads();

        #pragma unroll
        for (int ii = 0; ii < 4; ii++) {
            int ic = ph*4 + ii;
            u64 wpk[9];
            #pragma unroll
            for (int k = 0; k < 9; k++) wpk[k] = dup2(Wsmt[(ic*9 + k)*8 + oo]);
            u64 w1pk = dup2(Wsmt1[ic*8 + oo]);

            #pragma unroll
            for (int ky = 0; ky < 3; ky++) {
                const u64* A64 = reinterpret_cast<const u64*>(
                    &tileA[ii*TCH18 + (h + ky)*A_RS]);
                const u64* B64 = reinterpret_cast<const u64*>(
                    &tileB[ii*TCH18 + (h + ky)*A_RS]);
                u64 sp = A64[base];
                #pragma unroll
                for (int pl = 0; pl < 8; pl++) {
                    u64 e  = B64[base + pl];
                    u64 sn = A64[base + pl + 1];
                    FMA2(acc[pl], wpk[ky*3 + 0], sp);
                    FMA2(acc[pl], wpk[ky*3 + 1], e);
                    FMA2(acc[pl], wpk[ky*3 + 2], sn);
                    if (ky == 1) FMA2(acc1[pl], w1pk, e);   // 1x1 conv, center row
                    sp = sn;
                }
            }
        }
    }

    // store + bn partials
    int h_out = 16*hh + h;
    int og = oh*8 + oo;
    size_t ob = sbase + (size_t)og*1024 + h_out*32 + wh*16;
    u64* outp2 = reinterpret_cast<u64*>(&g_c2[ob]);
    u64* outp1 = reinterpret_cast<u64*>(&g_c1[ob]);
    float s2 = 0.f, q2 = 0.f, s1 = 0.f, q1 = 0.f;
    #pragma unroll
    for (int pl = 0; pl < 8; pl++) {
        u64 a = acc[pl], b = acc1[pl];
        outp2[pl] = a;
        outp1[pl] = b;
        float alo = __uint_as_float((unsigned)(a & 0xffffffffu));
        float ahi = __uint_as_float((unsigned)(a >> 32));
        float blo = __uint_as_float((unsigned)(b & 0xffffffffu));
        float bhi = __uint_as_float((unsigned)(b >> 32));
        s2 += alo + ahi; q2 += alo*alo + ahi*ahi;
        s1 += blo + bhi; q1 += blo*blo + bhi*bhi;
    }
    // lane = (h&1)*16 + wh*8 + oo: fold h-pair (xor16) then wh (xor8)
    s2 += __shfl_xor_sync(0xffffffffu, s2, 16);
    q2 += __shfl_xor_sync(0xffffffffu, q2, 16);
    s2 += __shfl_xor_sync(0xffffffffu, s2, 8);
    q2 += __shfl_xor_sync(0xffffffffu, q2, 8);
    s1 += __shfl_xor_sync(0xffffffffu, s1, 16);
    q1 += __shfl_xor_sync(0xffffffffu, q1, 16);
    s1 += __shfl_xor_sync(0xffffffffu, s1, 8);
    q1 += __shfl_xor_sync(0xffffffffu, q1, 8);
    if ((tid & 31) < 8) {
        red2[tid >> 5][oo] = make_float2(s2, q2);
        red1[tid >> 5][oo] = make_float2(s1, q1);
    }
    __syncthreads();
    if (tid < 16) {
        int o8 = tid & 7;
        float S = 0.f, Q = 0.f;
        if (tid < 8) {
            #pragma unroll
            for (int wd = 0; wd < 8; wd++) { S += red2[wd][o8].x; Q += red2[wd][o8].y; }
            g_part_c2[(nb*16 + oh*8 + o8)*32 + tb*2 + hh] = make_float2(S, Q);
        } else {
            #pragma unroll
            for (int wd = 0; wd < 8; wd++) { S += red1[wd][o8].x; Q += red1[wd][o8].y; }
            g_part_c1[(nb*16 + oh*8 + o8)*32 + tb*2 + hh] = make_float2(S, Q);
        }
    }
}

// ============================================================
// K5: inline inv/c1/c2 stats + out = BN(rec)+BN(c1)+BN(c2). float4.
// c1/c2: 32 slots (one warp each); inv: 16 slots.
// ============================================================
__global__ void k_final(float* __restrict__ out,
                        const float* __restrict__ gi, const float* __restrict__ bi,
                        const float* __restrict__ g1, const float* __restrict__ b1,
                        const float* __restrict__ g2, const float* __restrict__ b2) {
    int blk = blockIdx.x, t = threadIdx.x;
    int ch = blk & 255;
    __shared__ float2 cf[3];
    if (t < 32) {                       // c1: 32 slots
        float2 p = g_part_c1[ch*32 + t];
        float s = p.x, q = p.y;
        #pragma unroll
        for (int off = 16; off; off >>= 1) {
            s += __shfl_down_sync(0xffffffffu, s, off);
            q += __shfl_down_sync(0xffffffffu, q, off);
        }
        if (t == 0) {
            float mean = s * (1.0f/16384.0f);
            float var  = q * (1.0f/16384.0f) - mean*mean;
            float a = g1[ch] * rsqrtf(var + 1e-5f);
            cf[1] = make_float2(a, b1[ch] - mean*a);
        }
    } else if (t < 64) {                // c2: 32 slots
        int lane = t - 32;
        float2 p = g_part_c2[ch*32 + lane];
        float s = p.x, q = p.y;
        #pragma unroll
        for (int off = 16; off; off >>= 1) {
            s += __shfl_down_sync(0xffffffffu, s, off);
            q += __shfl_down_sync(0xffffffffu, q, off);
        }
        if (lane == 0) {
            float mean = s * (1.0f/16384.0f);
            float var  = q * (1.0f/16384.0f) - mean*mean;
            float a = g2[ch] * rsqrtf(var + 1e-5f);
            cf[2] = make_float2(a, b2[ch] - mean*a);
        }
    } else if (t < 80) {                // inv: 16 slots (warp2 lanes 0-15)
        int lane = t - 64;
        float2 p = g_part_inv[ch*16 + lane];
        float s = p.x, q = p.y;
        #pragma unroll
        for (int off = 8; off; off >>= 1) {
            s += __shfl_down_sync(0x0000ffffu, s, off, 16);
            q += __shfl_down_sync(0x0000ffffu, q, off, 16);
        }
        if (lane == 0) {
            float mean = s * (1.0f/16384.0f);
            float var  = q * (1.0f/16384.0f) - mean*mean;
            float a = gi[ch] * rsqrtf(var + 1e-5f);
            cf[0] = make_float2(a, bi[ch] - mean*a);
        }
    }
    __syncthreads();

    size_t base = (size_t)blk * 1024 + t * 4;
    float4 r  = *reinterpret_cast<const float4*>(&g_rec[base]);
    float4 u1 = *reinterpret_cast<const float4*>(&g_c1[base]);
    float4 u2 = *reinterpret_cast<const float4*>(&g_c2[base]);
    float2 A = cf[0], B = cf[1], C = cf[2];
    float4 o;
    o.x = (r.x*A.x + A.y) + (u1.x*B.x + B.y) + (u2.x*C.x + C.y);
    o.y = (r.y*A.x + A.y) + (u1.y*B.x + B.y) + (u2.y*C.x + C.y);
    o.z = (r.z*A.x + A.y) + (u1.z*B.x + B.y) + (u2.z*C.x + C.y);
    o.w = (r.w*A.x + A.y) + (u1.w*B.x + B.y) + (u2.w*C.x + C.y);
    *reinterpret_cast<float4*>(&out[base]) = o;
}

// ============================================================
extern "C" void kernel_launch(void* const* d_in, const int* in_sizes, int n_in,
                              void* d_out, int out_size) {
    const float* x        = (const float*)d_in[0];
    const float* haar_w   = (const float*)d_in[1];
    const float* conv1_w  = (const float*)d_in[2];
    const float* conv2_w  = (const float*)d_in[4];
    const float* bn_fwd_g = (const float*)d_in[6];
    const float* bn_fwd_b = (const float*)d_in[7];
    const float* bn_mul_g = (const float*)d_in[8];
    const float* bn_mul_b = (const float*)d_in[9];
    const float* bn_inv_g = (const float*)d_in[10];
    const float* bn_inv_b = (const float*)d_in[11];
    const float* bn_c1_g  = (const float*)d_in[12];
    const float* bn_c1_b  = (const float*)d_in[13];
    const float* bn_c2_g  = (const float*)d_in[14];
    const float* bn_c2_b  = (const float*)d_in[15];
    float* out = (float*)d_out;

    k_lif_haarw<<<2048, 256>>>(x);
    k_haarh_gate<<<4096, 256>>>(bn_fwd_g, bn_fwd_b);
    k_mix_inv<<<256, 256>>>(haar_w, bn_mul_g, bn_mul_b);
    k_convs<<<1024, 256>>>(conv2_w, conv1_w);
    k_final<<<4096, 256>>>(out, bn_inv_g, bn_inv_b,
                           bn_c1_g, bn_c1_b, bn_c2_g, bn_c2_b);
}

// round 17
// speedup vs baseline: 1.0332x; 1.0332x over previous
#include <cuda_runtime.h>
#include <math.h>

#define RS2 0.70710678f // 1/sqrt(2)

typedef unsigned long long u64;

// packed f32x2 FMA (lanewise fp32 fma): d = a*b + d
#define FMA2(d, a, b) asm("fma.rn.f32x2 %0, %1, %2, %0;" : "+l"(d) : "l"(a), "l"(b))

__device__ __forceinline__ u64 dup2(float w) {
    u64 r;
    asm("mov.b64 %0, {%1, %1};" : "=l"(r) : "r"(__float_as_uint(w)));
    return r;
}

// ---- scratch (device globals; no allocation allowed) ----
__device__ float g_s  [4*4*256*32*32];      // spikes (0/1)
__device__ float g_l1 [16*512*32*16];       // pre-BN level-1 coeffs
__device__ float g_l2 [16*1024*16*16];      // pre-BN level-2 coeffs
__device__ float g_rec[16*256*32*32];       // pre-BN reconstruction
__device__ float g_c1 [16*256*32*32];       // pre-BN conv1 out
__device__ float g_c2 [16*256*32*32];       // pre-BN conv2 out
// per-(channel, slot) partial (sum, sumsq) — fixed slots => deterministic
__device__ float2 g_part_fwd[512*8];
__device__ float2 g_part_mul[1024*16];
__device__ float2 g_part_inv[256*16];
__device__ float2 g_part_c1 [256*32];
__device__ float2 g_part_c2 [256*32];

// ============================================================
// K1: LIF over T + Haar along W + L1 gate + bn_fwd partials
// ============================================================
__global__ void k_lif_haarw(const float* __restrict__ x) {
    int blk = blockIdx.x, t = threadIdx.x;
    int idx = blk * 256 + t;
    int wp = idx & 15;
    int h  = (idx >> 4) & 31;
    int c  = (idx >> 9) & 255;
    int b  = idx >> 17;

    float v0 = 0.f, v1 = 0.f;
    float4 ps = make_float4(0.f, 0.f, 0.f, 0.f);
    #pragma unroll
    for (int tt = 0; tt < 4; tt++) {
        size_t base = ((((size_t)tt*4 + b)*256 + c)*32 + h)*32 + 2*wp;
        float2 xx = *reinterpret_cast<const float2*>(&x[base]);
        v0 += (xx.x - v0) * 0.5f;
        float s0 = (v0 >= 1.0f) ? 1.0f : 0.0f;
        v0 *= (1.0f - s0);
        v1 += (xx.y - v1) * 0.5f;
        float s1 = (v1 >= 1.0f) ? 1.0f : 0.0f;
        v1 *= (1.0f - s1);
        *reinterpret_cast<float2*>(&g_s[base]) = make_float2(s0, s1);

        float low  = RS2 * (s0 + s1);
        float high = RS2 * (s0 - s1);
        if (fabsf(low)  < 0.5f) low  = 0.f;
        if (fabsf(high) < 0.5f) high = 0.f;
        int tb = tt*4 + b;
        size_t l1b = (((size_t)tb*512 + c)*32 + h)*16 + wp;
        g_l1[l1b]          = low;
        g_l1[l1b + 131072] = high;
        ps.x += low;  ps.y += low*low;
        ps.z += high; ps.w += high*high;
    }
    #pragma unroll
    for (int off = 16; off; off >>= 1) {
        ps.x += __shfl_down_sync(0xffffffffu, ps.x, off);
        ps.y += __shfl_down_sync(0xffffffffu, ps.y, off);
        ps.z += __shfl_down_sync(0xffffffffu, ps.z, off);
        ps.w += __shfl_down_sync(0xffffffffu, ps.w, off);
    }
    __shared__ float4 wsum[8];
    if ((t & 31) == 0) wsum[t >> 5] = ps;
    __syncthreads();
    if (t == 0) {
        float4 a = wsum[0];
        #pragma unroll
        for (int i = 1; i < 8; i++) {
            float4 w4 = wsum[i];
            a.x += w4.x; a.y += w4.y; a.z += w4.z; a.w += w4.w;
        }
        int slot = ((blk >> 9) << 1) | (blk & 1);   // b*2 + hhalf
        int cc   = (blk >> 1) & 255;
        g_part_fwd[cc*8 + slot]         = make_float2(a.x, a.y);
        g_part_fwd[(256 + cc)*8 + slot] = make_float2(a.z, a.w);
    }
}

// ============================================================
// K2: inline bn_fwd stats + Haar along H + threshold + band gate
//     + bn_mul partials. block <-> (tb, c)
// ============================================================
__global__ void k_haarh_gate(const float* __restrict__ gf,
                             const float* __restrict__ bf) {
    int tb = blockIdx.x >> 8;
    int c  = blockIdx.x & 255;
    int t  = threadIdx.x;

    __shared__ float2 coef[2];
    if (t < 16) {
        int chn = (t < 8) ? c : 256 + c;
        float2 p = g_part_fwd[chn*8 + (t & 7)];
        float s = p.x, q = p.y;
        #pragma unroll
        for (int off = 4; off; off >>= 1) {
            s += __shfl_down_sync(0xffffu, s, off, 8);
            q += __shfl_down_sync(0xffffu, q, off, 8);
        }
        if ((t & 7) == 0) {
            float mean = s * (1.0f/8192.0f);
            float var  = q * (1.0f/8192.0f) - mean*mean;
            float a = gf[chn] * rsqrtf(var + 1e-5f);
            coef[t >> 3] = make_float2(a, bf[chn] - mean*a);
        }
    }
    __syncthreads();

    int v = t >> 4, w = t & 15;
    float alo = coef[0].x, clo = coef[0].y;
    float ahi = coef[1].x, chi = coef[1].y;

    size_t lo_base = ((size_t)tb*512 + c) * 512;
    size_t hi_base = lo_base + 131072;
    float a0 = g_l1[lo_base + (2*v  )*16 + w] * alo + clo;
    float a1 = g_l1[lo_base + (2*v+1)*16 + w] * alo + clo;
    float b0 = g_l1[hi_base + (2*v  )*16 + w] * ahi + chi;
    float b1 = g_l1[hi_base + (2*v+1)*16 + w] * ahi + chi;

    float LL = RS2 * (a0 + a1);
    float HL = RS2 * (a0 - a1);
    float LH = RS2 * (b0 + b1);
    float HH = RS2 * (b0 - b1);
    if (fabsf(LL) < 0.5f) LL = 0.f;
    if (fabsf(HL) < 0.5f) HL = 0.f;
    if (fabsf(LH) < 0.5f) LH = 0.f;
    if (fabsf(HH) < 0.5f) HH = 0.f;

    float4 vs = make_float4(LL, HL, LH, HH);
    float4 vq = make_float4(LL*LL, HL*HL, LH*LH, HH*HH);
    #pragma unroll
    for (int off = 16; off; off >>= 1) {
        vs.x += __shfl_down_sync(0xffffffffu, vs.x, off);
        vs.y += __shfl_down_sync(0xffffffffu, vs.y, off);
        vs.z += __shfl_down_sync(0xffffffffu, vs.z, off);
        vs.w += __shfl_down_sync(0xffffffffu, vs.w, off);
        vq.x += __shfl_down_sync(0xffffffffu, vq.x, off);
        vq.y += __shfl_down_sync(0xffffffffu, vq.y, off);
        vq.z += __shfl_down_sync(0xffffffffu, vq.z, off);
        vq.w += __shfl_down_sync(0xffffffffu, vq.w, off);
    }
    __shared__ float4 wS[8], wQ[8];
    __shared__ float4 flags;
    if ((t & 31) == 0) { wS[t >> 5] = vs; wQ[t >> 5] = vq; }
    __syncthreads();
    if (t == 0) {
        float4 S = wS[0], Q = wQ[0];
        #pragma unroll
        for (int i = 1; i < 8; i++) {
            float4 a = wS[i], b4 = wQ[i];
            S.x += a.x;  S.y += a.y;  S.z += a.z;  S.w += a.w;
            Q.x += b4.x; Q.y += b4.y; Q.z += b4.z; Q.w += b4.w;
        }
        const float inv = 1.0f / 256.0f;
        float4 f = make_float4(Q.x*inv > 0.01f ? 1.f : 0.f,
                               Q.y*inv > 0.02f ? 1.f : 0.f,
                               Q.z*inv > 0.02f ? 1.f : 0.f,
                               Q.w*inv > 0.05f ? 1.f : 0.f);
        flags = f;
        g_part_mul[(c      )*16 + tb] = make_float2(f.x*S.x, f.x*Q.x);
        g_part_mul[(c + 256)*16 + tb] = make_float2(f.y*S.y, f.y*Q.y);
        g_part_mul[(c + 512)*16 + tb] = make_float2(f.z*S.z, f.z*Q.z);
        g_part_mul[(c + 768)*16 + tb] = make_float2(f.w*S.w, f.w*Q.w);
    }
    __syncthreads();

    size_t ob = (((size_t)tb*1024 + c)*16 + v)*16 + w;
    g_l2[ob]          = LL * flags.x;
    g_l2[ob + 65536]  = HL * flags.y;
    g_l2[ob + 131072] = LH * flags.z;
    g_l2[ob + 196608] = HH * flags.w;
}

// ============================================================
// K3 (fused): bn_mul stats + 16x16 channel mix for all 4 subbands of a
// base group + inverse Haar butterfly + bn_inv partials.
// ============================================================
__global__ void k_mix_inv(const float* __restrict__ hw,
                          const float* __restrict__ gm,
                          const float* __restrict__ bm) {
    int tb = blockIdx.x >> 4;
    int gb = blockIdx.x & 15;
    int t  = threadIdx.x;

    __shared__ float Wsm[4][256];
    __shared__ float sc[64], of[64];
    __shared__ float2 wred[8][16];

    #pragma unroll
    for (int sb = 0; sb < 4; sb++)
        Wsm[sb][t] = hw[(4*sb + (gb >> 2)) * 256 + t];

    {
        int chl = t >> 2, j = t & 3;
        int sb = chl >> 4, d = chl & 15;
        int ch = sb*256 + gb*16 + d;
        float s = 0.f, q = 0.f;
        #pragma unroll
        for (int k = 0; k < 4; k++) {
            float2 p = g_part_mul[ch*16 + j + 4*k];
            s += p.x; q += p.y;
        }
        s += __shfl_down_sync(0xffffffffu, s, 2, 4);
        q += __shfl_down_sync(0xffffffffu, q, 2, 4);
        s += __shfl_down_sync(0xffffffffu, s, 1, 4);
        q += __shfl_down_sync(0xffffffffu, q, 1, 4);
        if (j == 0) {
            float mean = s * (1.0f/4096.0f);
            float var  = q * (1.0f/4096.0f) - mean*mean;
            float a = gm[ch] * rsqrtf(var + 1e-5f);
            sc[chl] = a;
            of[chl] = bm[ch] - mean*a;
        }
    }
    __syncthreads();

    float acc[4][16];
    #pragma unroll
    for (int sb = 0; sb < 4; sb++)
        #pragma unroll
        for (int k = 0; k < 16; k++) acc[sb][k] = 0.f;

    #pragma unroll
    for (int sb = 0; sb < 4; sb++) {
        size_t base = ((size_t)tb*1024 + sb*256 + gb*16) * 256 + t;
        #pragma unroll
        for (int d = 0; d < 16; d++) {
            float in = g_l2[base + (size_t)d*256] * sc[sb*16+d] + of[sb*16+d];
            #pragma unroll
            for (int k = 0; k < 16; k++) acc[sb][k] += in * Wsm[sb][d*16 + k];
        }
    }

    int v = t >> 4, w = t & 15;
    int warp = t >> 5;
    #pragma unroll
    for (int k = 0; k < 16; k++) {
        float LL = acc[0][k], HL = acc[1][k], LH = acc[2][k], HH = acc[3][k];
        float lo0 = RS2*(LL + HL), lo1 = RS2*(LL - HL);
        float hi0 = RS2*(LH + HH), hi1 = RS2*(LH - HH);
        float r00 = RS2*(lo0 + hi0), r01 = RS2*(lo0 - hi0);
        float r10 = RS2*(lo1 + hi1), r11 = RS2*(lo1 - hi1);

        size_t rb = (((size_t)tb*256 + gb*16 + k)*32 + 2*v)*32 + 2*w;
        *reinterpret_cast<float2*>(&g_rec[rb])      = make_float2(r00, r01);
        *reinterpret_cast<float2*>(&g_rec[rb + 32]) = make_float2(r10, r11);

        float s = r00 + r01 + r10 + r11;
        float q = r00*r00 + r01*r01 + r10*r10 + r11*r11;
        #pragma unroll
        for (int off = 16; off; off >>= 1) {
            s += __shfl_down_sync(0xffffffffu, s, off);
            q += __shfl_down_sync(0xffffffffu, q, off);
        }
        if ((t & 31) == 0) wred[warp][k] = make_float2(s, q);
    }
    __syncthreads();
    if (t < 16) {
        float S = 0.f, Q = 0.f;
        #pragma unroll
        for (int wd = 0; wd < 8; wd++) { S += wred[wd][t].x; Q += wred[wd][t].y; }
        g_part_inv[(gb*16 + t)*16 + tb] = make_float2(S, Q);
    }
}

// ============================================================
// K4 (fused convs v2): 3x3 + 1x1 grouped conv, FFMA2.
// - LDS.128 (ulonglong2) loads: 9 shared loads per (ii,ky) instead of 17.
// - Double-buffered tiles: staging of phase ph+1 overlaps compute of ph.
// grid 1024 = im x oh(2) x hh(2); 256 thr = 8 oo x 2 wh x 16 h.
// Half-height tiles (18 rows incl. halo, stride 36, conflict-free).
// + bn_c1/bn_c2 partials (32 slots: tb*2+hh).
// ============================================================
#define A_RS 36
#define TCH18 (18 * A_RS)   // 648 floats per channel slab

__global__ __launch_bounds__(256) void k_convs(const float* __restrict__ w2,
                                               const float* __restrict__ w1) {
    int blk = blockIdx.x;                 // 1024
    int im = blk >> 2;
    int oh = (blk >> 1) & 1;
    int hh = blk & 1;
    int tb = im >> 4, nb = im & 15;
    __shared__ __align__(16) float tileA[2][4 * TCH18];  // 20736 B
    __shared__ __align__(16) float tileB[2][4 * TCH18];  // 20736 B
    __shared__ float Wsmt[1152];                         //  4608 B [ic*9+k][oo]
    __shared__ float Wsmt1[128];                         //   512 B [ic][oo]
    __shared__ float2 red2[8][8], red1[8][8];            //  1024 B
    int tid = threadIdx.x;
    int oo = tid & 7;
    int wh = (tid >> 3) & 1;
    int h  = tid >> 4;                    // 0..15

    for (int idx = tid; idx < 1152; idx += 256) {
        int o8 = idx & 7, rest = idx >> 3;          // rest = ic*9+k
        Wsmt[idx] = w2[(oh*8 + o8)*144 + rest];
    }
    if (tid < 128) {
        int o8 = tid & 7, ic = tid >> 3;
        Wsmt1[tid] = w1[(oh*8 + o8)*16 + ic];
    }
    for (int idx = tid; idx < 2*4*TCH18; idx += 256) {
        tileA[0][idx] = 0.f; tileB[0][idx] = 0.f;   // zero both buffers (flat)
    }
    __syncthreads();   // zeroing complete before first staging

    size_t sbase = (size_t)im * 16384;

    // ---- staging helper (ph -> buffer b) ----
    #define STAGE(ph_, b_)                                                     \
    do {                                                                       \
        for (int idx = tid; idx < 576; idx += 256) {                           \
            int ii  = idx / 144;                                               \
            int rem = idx - ii*144;                                            \
            int rr  = rem >> 3;                                                \
            int ww4 = (rem & 7) * 4;                                           \
            int r = 16*hh + rr - 1;                                            \
            if (r >= 0 && r < 32) {                                            \
                float4 val = *reinterpret_cast<const float4*>(                 \
                    &g_s[sbase + (size_t)((ph_)*4 + ii)*1024 + r*32 + ww4]);   \
                float* dA = &tileA[b_][ii*TCH18 + rr*A_RS + ww4 + 1];          \
                dA[0] = val.x; dA[1] = val.y; dA[2] = val.z; dA[3] = val.w;    \
                *reinterpret_cast<float4*>(                                    \
                    &tileB[b_][ii*TCH18 + rr*A_RS + ww4]) = val;               \
            }                                                                  \
        }                                                                      \
    } while (0)

    STAGE(0, 0);
    __syncthreads();

    u64 acc[8], acc1[8];
    #pragma unroll
    for (int pl = 0; pl < 8; pl++) { acc[pl] = 0ull; acc1[pl] = 0ull; }

    for (int ph = 0; ph < 4; ph++) {
        int buf = ph & 1;
        if (ph < 3) STAGE(ph + 1, buf ^ 1);    // overlaps with compute below

        #pragma unroll
        for (int ii = 0; ii < 4; ii++) {
            int ic = ph*4 + ii;
            u64 wpk[9];
            #pragma unroll
            for (int k = 0; k < 9; k++) wpk[k] = dup2(Wsmt[(ic*9 + k)*8 + oo]);
            u64 w1pk = dup2(Wsmt1[ic*8 + oo]);

            #pragma unroll
            for (int ky = 0; ky < 3; ky++) {
                const float* rowA = &tileA[buf][ii*TCH18 + (h + ky)*A_RS];
                const float* rowB = &tileB[buf][ii*TCH18 + (h + ky)*A_RS];
                const ulonglong2* A2 = reinterpret_cast<const ulonglong2*>(rowA) + wh*4;
                const ulonglong2* B2 = reinterpret_cast<const ulonglong2*>(rowB) + wh*4;
                ulonglong2 a0 = A2[0], a1 = A2[1], a2v = A2[2], a3 = A2[3];
                u64 a8 = reinterpret_cast<const u64*>(rowA)[wh*8 + 8];
                ulonglong2 b0 = B2[0], b1 = B2[1], b2v = B2[2], b3 = B2[3];

                u64 S[9] = {a0.x, a0.y, a1.x, a1.y, a2v.x, a2v.y, a3.x, a3.y, a8};
                u64 E[8] = {b0.x, b0.y, b1.x, b1.y, b2v.x, b2v.y, b3.x, b3.y};

                #pragma unroll
                for (int pl = 0; pl < 8; pl++) {
                    FMA2(acc[pl], wpk[ky*3 + 0], S[pl]);
                    FMA2(acc[pl], wpk[ky*3 + 1], E[pl]);
                    FMA2(acc[pl], wpk[ky*3 + 2], S[pl + 1]);
                    if (ky == 1) FMA2(acc1[pl], w1pk, E[pl]);
                }
            }
        }
        __syncthreads();   // staging(ph+1) done; compute(ph) done before reuse
    }
    #undef STAGE

    // store + bn partials
    int h_out = 16*hh + h;
    int og = oh*8 + oo;
    size_t ob = sbase + (size_t)og*1024 + h_out*32 + wh*16;
    u64* outp2 = reinterpret_cast<u64*>(&g_c2[ob]);
    u64* outp1 = reinterpret_cast<u64*>(&g_c1[ob]);
    float s2 = 0.f, q2 = 0.f, s1 = 0.f, q1 = 0.f;
    #pragma unroll
    for (int pl = 0; pl < 8; pl++) {
        u64 a = acc[pl], b = acc1[pl];
        outp2[pl] = a;
        outp1[pl] = b;
        float alo = __uint_as_float((unsigned)(a & 0xffffffffu));
        float ahi = __uint_as_float((unsigned)(a >> 32));
        float blo = __uint_as_float((unsigned)(b & 0xffffffffu));
        float bhi = __uint_as_float((unsigned)(b >> 32));
        s2 += alo + ahi; q2 += alo*alo + ahi*ahi;
        s1 += blo + bhi; q1 += blo*blo + bhi*bhi;
    }
    // lane = (h&1)*16 + wh*8 + oo: fold h-pair (xor16) then wh (xor8)
    s2 += __shfl_xor_sync(0xffffffffu, s2, 16);
    q2 += __shfl_xor_sync(0xffffffffu, q2, 16);
    s2 += __shfl_xor_sync(0xffffffffu, s2, 8);
    q2 += __shfl_xor_sync(0xffffffffu, q2, 8);
    s1 += __shfl_xor_sync(0xffffffffu, s1, 16);
    q1 += __shfl_xor_sync(0xffffffffu, q1, 16);
    s1 += __shfl_xor_sync(0xffffffffu, s1, 8);
    q1 += __shfl_xor_sync(0xffffffffu, q1, 8);
    if ((tid & 31) < 8) {
        red2[tid >> 5][oo] = make_float2(s2, q2);
        red1[tid >> 5][oo] = make_float2(s1, q1);
    }
    __syncthreads();
    if (tid < 16) {
        int o8 = tid & 7;
        float S = 0.f, Q = 0.f;
        if (tid < 8) {
            #pragma unroll
            for (int wd = 0; wd < 8; wd++) { S += red2[wd][o8].x; Q += red2[wd][o8].y; }
            g_part_c2[(nb*16 + oh*8 + o8)*32 + tb*2 + hh] = make_float2(S, Q);
        } else {
            #pragma unroll
            for (int wd = 0; wd < 8; wd++) { S += red1[wd][o8].x; Q += red1[wd][o8].y; }
            g_part_c1[(nb*16 + oh*8 + o8)*32 + tb*2 + hh] = make_float2(S, Q);
        }
    }
}

// ============================================================
// K5: inline inv/c1/c2 stats + out = BN(rec)+BN(c1)+BN(c2). float4.
// c1/c2: 32 slots (one warp each); inv: 16 slots.
// ============================================================
__global__ void k_final(float* __restrict__ out,
                        const float* __restrict__ gi, const float* __restrict__ bi,
                        const float* __restrict__ g1, const float* __restrict__ b1,
                        const float* __restrict__ g2, const float* __restrict__ b2) {
    int blk = blockIdx.x, t = threadIdx.x;
    int ch = blk & 255;
    __shared__ float2 cf[3];
    if (t < 32) {                       // c1: 32 slots
        float2 p = g_part_c1[ch*32 + t];
        float s = p.x, q = p.y;
        #pragma unroll
        for (int off = 16; off; off >>= 1) {
            s += __shfl_down_sync(0xffffffffu, s, off);
            q += __shfl_down_sync(0xffffffffu, q, off);
        }
        if (t == 0) {
            float mean = s * (1.0f/16384.0f);
            float var  = q * (1.0f/16384.0f) - mean*mean;
            float a = g1[ch] * rsqrtf(var + 1e-5f);
            cf[1] = make_float2(a, b1[ch] - mean*a);
        }
    } else if (t < 64) {                // c2: 32 slots
        int lane = t - 32;
        float2 p = g_part_c2[ch*32 + lane];
        float s = p.x, q = p.y;
        #pragma unroll
        for (int off = 16; off; off >>= 1) {
            s += __shfl_down_sync(0xffffffffu, s, off);
            q += __shfl_down_sync(0xffffffffu, q, off);
        }
        if (lane == 0) {
            float mean = s * (1.0f/16384.0f);
            float var  = q * (1.0f/16384.0f) - mean*mean;
            float a = g2[ch] * rsqrtf(var + 1e-5f);
            cf[2] = make_float2(a, b2[ch] - mean*a);
        }
    } else if (t < 80) {                // inv: 16 slots (warp2 lanes 0-15)
        int lane = t - 64;
        float2 p = g_part_inv[ch*16 + lane];
        float s = p.x, q = p.y;
        #pragma unroll
        for (int off = 8; off; off >>= 1) {
            s += __shfl_down_sync(0x0000ffffu, s, off, 16);
            q += __shfl_down_sync(0x0000ffffu, q, off, 16);
        }
        if (lane == 0) {
            float mean = s * (1.0f/16384.0f);
            float var  = q * (1.0f/16384.0f) - mean*mean;
            float a = gi[ch] * rsqrtf(var + 1e-5f);
            cf[0] = make_float2(a, bi[ch] - mean*a);
        }
    }
    __syncthreads();

    size_t base = (size_t)blk * 1024 + t * 4;
    float4 r  = *reinterpret_cast<const float4*>(&g_rec[base]);
    float4 u1 = *reinterpret_cast<const float4*>(&g_c1[base]);
    float4 u2 = *reinterpret_cast<const float4*>(&g_c2[base]);
    float2 A = cf[0], B = cf[1], C = cf[2];
    float4 o;
    o.x = (r.x*A.x + A.y) + (u1.x*B.x + B.y) + (u2.x*C.x + C.y);
    o.y = (r.y*A.x + A.y) + (u1.y*B.x + B.y) + (u2.y*C.x + C.y);
    o.z = (r.z*A.x + A.y) + (u1.z*B.x + B.y) + (u2.z*C.x + C.y);
    o.w = (r.w*A.x + A.y) + (u1.w*B.x + B.y) + (u2.w*C.x + C.y);
    *reinterpret_cast<float4*>(&out[base]) = o;
}

// ============================================================
extern "C" void kernel_launch(void* const* d_in, const int* in_sizes, int n_in,
                              void* d_out, int out_size) {
    const float* x        = (const float*)d_in[0];
    const float* haar_w   = (const float*)d_in[1];
    const float* conv1_w  = (const float*)d_in[2];
    const float* conv2_w  = (const float*)d_in[4];
    const float* bn_fwd_g = (const float*)d_in[6];
    const float* bn_fwd_b = (const float*)d_in[7];
    const float* bn_mul_g = (const float*)d_in[8];
    const float* bn_mul_b = (const float*)d_in[9];
    const float* bn_inv_g = (const float*)d_in[10];
    const float* bn_inv_b = (const float*)d_in[11];
    const float* bn_c1_g  = (const float*)d_in[12];
    const float* bn_c1_b  = (const float*)d_in[13];
    const float* bn_c2_g  = (const float*)d_in[14];
    const float* bn_c2_b  = (const float*)d_in[15];
    float* out = (float*)d_out;

    k_lif_haarw<<<2048, 256>>>(x);
    k_haarh_gate<<<4096, 256>>>(bn_fwd_g, bn_fwd_b);
    k_mix_inv<<<256, 256>>>(haar_w, bn_mul_g, bn_mul_b);
    k_convs<<<1024, 256>>>(conv2_w, conv1_w);
    k_final<<<4096, 256>>>(out, bn_inv_g, bn_inv_b,
                           bn_c1_g, bn_c1_b, bn_c2_g, bn_c2_b);
}